// round 1
// baseline (speedup 1.0000x reference)
#include <cuda_runtime.h>
#include <stdint.h>

// Problem constants
#define TT 2048
#define BB 128
#define KK 64

// ---------------------------------------------------------------------------
// Threefry-2x32, 20 rounds, exactly as jax._src.prng.threefry2x32
// ---------------------------------------------------------------------------
__device__ __forceinline__ uint2 tf2x32(uint32_t k0, uint32_t k1,
                                        uint32_t x0, uint32_t x1) {
    uint32_t ks2 = k0 ^ k1 ^ 0x1BD11BDAu;
    x0 += k0; x1 += k1;
#define TFR(r) { x0 += x1; x1 = __funnelshift_l(x1, x1, (r)); x1 ^= x0; }
    TFR(13) TFR(15) TFR(26) TFR(6)
    x0 += k1; x1 += ks2 + 1u;
    TFR(17) TFR(29) TFR(16) TFR(24)
    x0 += ks2; x1 += k0 + 2u;
    TFR(13) TFR(15) TFR(26) TFR(6)
    x0 += k0; x1 += k1 + 3u;
    TFR(17) TFR(29) TFR(16) TFR(24)
    x0 += k1; x1 += ks2 + 4u;
    TFR(13) TFR(15) TFR(26) TFR(6)
    x0 += ks2; x1 += k0 + 5u;
#undef TFR
    return make_uint2(x0, x1);
}

// bits -> uniform [0,1): bitcast((bits>>9)|0x3f800000) - 1
__device__ __forceinline__ float bits_to_u01(uint32_t bits) {
    return __uint_as_float((bits >> 9) | 0x3f800000u) - 1.0f;
}

// XLA/CHLO ErfInv32 polynomial (Giles)
__device__ __forceinline__ float erfinv_xla(float x) {
    float w = -log1pf(-x * x);
    float p;
    if (w < 5.0f) {
        w = w - 2.5f;
        p = 2.81022636e-08f;
        p = fmaf(p, w, 3.43273939e-07f);
        p = fmaf(p, w, -3.5233877e-06f);
        p = fmaf(p, w, -4.39150654e-06f);
        p = fmaf(p, w, 0.00021858087f);
        p = fmaf(p, w, -0.00125372503f);
        p = fmaf(p, w, -0.00417768164f);
        p = fmaf(p, w, 0.246640727f);
        p = fmaf(p, w, 1.50140941f);
    } else {
        w = sqrtf(w) - 3.0f;
        p = -0.000200214257f;
        p = fmaf(p, w, 0.000100950558f);
        p = fmaf(p, w, 0.00134934322f);
        p = fmaf(p, w, -0.00367342844f);
        p = fmaf(p, w, 0.00573950773f);
        p = fmaf(p, w, -0.0076224613f);
        p = fmaf(p, w, 0.00943887047f);
        p = fmaf(p, w, 1.00167406f);
        p = fmaf(p, w, 2.83297682f);
    }
    return p * x;
}

// gumbel = -log(-log(max(tiny, u)))   (uniform(minval=tiny, maxval=1))
__device__ __forceinline__ float gumbel_from_bits(uint32_t bits) {
    float u = bits_to_u01(bits);
    float v = fmaxf(u, 1.17549435082228751e-38f);
    return -logf(-logf(v));
}

// ---------------------------------------------------------------------------
// Fill the 4 constant columns of pf_out once (they are garch_params broadcast)
// pf_out[(t*K*B + k*B + b)*5 + c] = params[c], c in 0..3
// ---------------------------------------------------------------------------
__global__ void fill_const_kernel(const float* __restrict__ params,
                                  float* __restrict__ pf) {
    const float p0 = params[0], p1 = params[1], p2 = params[2], p3 = params[3];
    const size_t n = (size_t)TT * KK * BB;
    for (size_t idx = (size_t)blockIdx.x * blockDim.x + threadIdx.x; idx < n;
         idx += (size_t)gridDim.x * blockDim.x) {
        float* o = pf + idx * 5;
        o[0] = p0; o[1] = p1; o[2] = p2; o[3] = p3;
    }
}

// ---------------------------------------------------------------------------
// Main persistent kernel: one CTA per batch element b, full T-scan inside.
// 256 threads: warp 0 owns the 64-particle state (2 particles per lane),
// all 8 warps cooperate on the 64x64 gumbel+argmax per step.
// ---------------------------------------------------------------------------
__global__ void __launch_bounds__(256, 1)
garch_pf_kernel(const float* __restrict__ obs,     // (B, T, 2)
                const float* __restrict__ vol0,    // (K*B, 1)
                const float* __restrict__ params,  // (4,)
                float* __restrict__ out) {
    const int b    = blockIdx.x;
    const int tid  = threadIdx.x;
    const int lane = tid & 31;
    const int warp = tid >> 5;

    __shared__ uint2 skey[TT];    // per-step key_t
    __shared__ uint2 sckey[TT];   // fold_in(key_t, 1)
    __shared__ float r_s[TT];     // obs[b, t, 0]
    __shared__ float logit_s[KK];
    __shared__ float nv_s[KK], wn_s[KK], q_s[KK];
    __shared__ float vol_s[KK], w_s[KK];
    __shared__ int   idx_s[KK];

    // One-time: per-step keys (split foldlike: key_t = tf(base, (0, t))),
    // categorical keys (fold_in: tf(key_t, (0,1))), and obs returns.
    for (int t = tid; t < TT; t += 256) {
        uint2 kt = tf2x32(0u, 42u, 0u, (uint32_t)t);
        skey[t]  = kt;
        sckey[t] = tf2x32(kt.x, kt.y, 0u, 1u);
        r_s[t]   = obs[((size_t)b * TT + t) * 2];
    }
    if (tid < 32) {
        vol_s[lane]      = vol0[lane * BB + b];
        vol_s[lane + 32] = vol0[(lane + 32) * BB + b];
        w_s[lane]        = 1.0f / 64.0f;
        w_s[lane + 32]   = 1.0f / 64.0f;
    }
    const float c0 = params[0], q1 = params[1], q2 = params[2], r1 = params[3];
    const float r1e = 0.001f * r1;   // (0.001 * r1) in f32, as XLA does
    __syncthreads();

    float* __restrict__ y_out = out;                       // (T, B, 1)
    float* __restrict__ pf    = out + (size_t)TT * BB;     // (T, K*B, 5)

    const float MINVAL_N = -0.99999994039535522f;  // nextafter(-1, 0) f32
    const float SQRT2    = (float)1.4142135623730951;
    const float LOG2PI   = (float)1.8378770664093453;
    const float ALPHA_F  = (float)0.3;
    const float UNIFW    = (float)((1.0 - 0.3) / 64.0);

    for (int t = 0; t < TT; t++) {
        // ---------------- Phase A: eps, vol update, weights, logits --------
        if (warp == 0) {
            const uint2 kt = skey[t];
            const float r    = r_s[t];
            const float rr   = r * r;         // r*r (loglik term)
            const float q2rr = (q2 * r) * r;  // q2*r*r, left-assoc like python
            float lw[2], nv[2];
#pragma unroll
            for (int h = 0; h < 2; h++) {
                const int pa = lane + h * 32;
                // eps bits: partitionable random_bits -> out0 ^ out1 of
                // tf(key_t, (0, flat_index)), flat = pa*B + b
                uint2 bl = tf2x32(kt.x, kt.y, 0u, (uint32_t)(pa * BB + b));
                float u  = bits_to_u01(bl.x ^ bl.y);
                float v  = u * 2.0f + MINVAL_N;   // (maxval-minval) rounds to 2.0f
                v = fmaxf(MINVAL_N, v);
                float eps = SQRT2 * erfinv_xla(v);
                float x   = ((c0 + q1 * vol_s[pa]) + q2rr) + r1e * eps;
                float nvv = fabsf(x) + (float)1e-8;
                nv[h] = nvv;
                float ll = -0.5f * ((rr / nvv + logf(nvv)) + LOG2PI);
                lw[h] = logf(w_s[pa] + (float)1e-12) + ll;
            }
            // logsumexp over 64 particles (warp-wide, 2/lane)
            float m = fmaxf(lw[0], lw[1]);
#pragma unroll
            for (int o = 16; o; o >>= 1)
                m = fmaxf(m, __shfl_xor_sync(0xffffffffu, m, o));
            float s = expf(lw[0] - m) + expf(lw[1] - m);
#pragma unroll
            for (int o = 16; o; o >>= 1)
                s += __shfl_xor_sync(0xffffffffu, s, o);
            float lse = logf(s) + m;
#pragma unroll
            for (int h = 0; h < 2; h++) {
                const int pa = lane + h * 32;
                float wn = expf(lw[h] - lse);
                float q  = ALPHA_F * wn + UNIFW;
                nv_s[pa]    = nv[h];
                wn_s[pa]    = wn;
                q_s[pa]     = q;
                logit_s[pa] = logf(q);
            }
        }
        __syncthreads();

        // ---------------- Phase B: gumbel + argmax over j (64x64) ----------
        {
            const uint2 ck = sckey[t];
            const uint32_t bb64 = (uint32_t)(b * KK);
#pragma unroll 2
            for (int ii = 0; ii < 8; ii++) {
                const int i = warp * 8 + ii;           // draw index (row of idx)
                const uint32_t cb = (uint32_t)i * 8192u + bb64;  // i*B*K + b*K
                uint2 g1 = tf2x32(ck.x, ck.y, 0u, cb + (uint32_t)lane);
                uint2 g2 = tf2x32(ck.x, ck.y, 0u, cb + (uint32_t)lane + 32u);
                float s1 = gumbel_from_bits(g1.x ^ g1.y) + logit_s[lane];
                float s2 = gumbel_from_bits(g2.x ^ g2.y) + logit_s[lane + 32];
                float best; int bj;
                if (s2 > s1) { best = s2; bj = lane + 32; }
                else         { best = s1; bj = lane; }
                // argmax reduction; ties -> lowest index (XLA argmax semantics)
#pragma unroll
                for (int o = 16; o; o >>= 1) {
                    float ov = __shfl_xor_sync(0xffffffffu, best, o);
                    int   oj = __shfl_xor_sync(0xffffffffu, bj, o);
                    if (ov > best || (ov == best && oj < bj)) { best = ov; bj = oj; }
                }
                if (lane == 0) idx_s[i] = bj;
            }
        }
        __syncthreads();

        // ---------------- Phase C: resample, normalize, outputs ------------
        if (warp == 0) {
            const int ia = idx_s[lane], ib = idx_s[lane + 32];
            float vra = nv_s[ia], vrb = nv_s[ib];
            float wra = wn_s[ia] / q_s[ia];
            float wrb = wn_s[ib] / q_s[ib];
            float ssum = wra + wrb;
#pragma unroll
            for (int o = 16; o; o >>= 1)
                ssum += __shfl_xor_sync(0xffffffffu, ssum, o);
            wra /= ssum; wrb /= ssum;
            vol_s[lane]      = vra; vol_s[lane + 32] = vrb;
            w_s[lane]        = wra; w_s[lane + 32]   = wrb;
            float y = vra * wra + vrb * wrb;
#pragma unroll
            for (int o = 16; o; o >>= 1)
                y += __shfl_xor_sync(0xffffffffu, y, o);
            if (lane == 0) y_out[(size_t)t * BB + b] = y;
            // vol column (c=4) of pf_out
            pf[((size_t)t * (KK * BB) + (size_t)lane * BB + b) * 5 + 4] = vra;
            pf[((size_t)t * (KK * BB) + (size_t)(lane + 32) * BB + b) * 5 + 4] = vrb;
        }
        __syncthreads();
    }
}

// ---------------------------------------------------------------------------
extern "C" void kernel_launch(void* const* d_in, const int* in_sizes, int n_in,
                              void* d_out, int out_size) {
    const float* obs    = (const float*)d_in[0];  // (128, 2048, 2)
    const float* vol0   = (const float*)d_in[1];  // (8192, 1)
    const float* params = (const float*)d_in[2];  // (4,)
    float* out = (float*)d_out;                   // y_out (T*B) ++ pf_out (T*K*B*5)

    float* pf = out + (size_t)TT * BB;
    fill_const_kernel<<<65536, 256>>>(params, pf);
    garch_pf_kernel<<<BB, 256>>>(obs, vol0, params, out);
}

// round 3
// speedup vs baseline: 1.4595x; 1.4595x over previous
#include <cuda_runtime.h>
#include <stdint.h>

// Problem constants
#define TT 2048
#define BB 128
#define KK 64
#define NTHREADS 576   // 18 warps: 0-1 = state (A/C), 2-17 = gumbel rows (4 each)

// ---------------------------------------------------------------------------
// Threefry-2x32, 20 rounds, exactly as jax._src.prng.threefry2x32
// ---------------------------------------------------------------------------
__device__ __forceinline__ uint2 tf2x32(uint32_t k0, uint32_t k1,
                                        uint32_t x0, uint32_t x1) {
    uint32_t ks2 = k0 ^ k1 ^ 0x1BD11BDAu;
    x0 += k0; x1 += k1;
#define TFR(r) { x0 += x1; x1 = __funnelshift_l(x1, x1, (r)); x1 ^= x0; }
    TFR(13) TFR(15) TFR(26) TFR(6)
    x0 += k1; x1 += ks2 + 1u;
    TFR(17) TFR(29) TFR(16) TFR(24)
    x0 += ks2; x1 += k0 + 2u;
    TFR(13) TFR(15) TFR(26) TFR(6)
    x0 += k0; x1 += k1 + 3u;
    TFR(17) TFR(29) TFR(16) TFR(24)
    x0 += k1; x1 += ks2 + 4u;
    TFR(13) TFR(15) TFR(26) TFR(6)
    x0 += ks2; x1 += k0 + 5u;
#undef TFR
    return make_uint2(x0, x1);
}

__device__ __forceinline__ float bits_to_u01(uint32_t bits) {
    return __uint_as_float((bits >> 9) | 0x3f800000u) - 1.0f;
}

// XLA/CHLO ErfInv32 polynomial (Giles) -- precise path (feeds state)
__device__ __forceinline__ float erfinv_xla(float x) {
    float w = -log1pf(-x * x);
    float p;
    if (w < 5.0f) {
        w = w - 2.5f;
        p = 2.81022636e-08f;
        p = fmaf(p, w, 3.43273939e-07f);
        p = fmaf(p, w, -3.5233877e-06f);
        p = fmaf(p, w, -4.39150654e-06f);
        p = fmaf(p, w, 0.00021858087f);
        p = fmaf(p, w, -0.00125372503f);
        p = fmaf(p, w, -0.00417768164f);
        p = fmaf(p, w, 0.246640727f);
        p = fmaf(p, w, 1.50140941f);
    } else {
        w = sqrtf(w) - 3.0f;
        p = -0.000200214257f;
        p = fmaf(p, w, 0.000100950558f);
        p = fmaf(p, w, 0.00134934322f);
        p = fmaf(p, w, -0.00367342844f);
        p = fmaf(p, w, 0.00573950773f);
        p = fmaf(p, w, -0.0076224613f);
        p = fmaf(p, w, 0.00943887047f);
        p = fmaf(p, w, 1.00167406f);
        p = fmaf(p, w, 2.83297682f);
    }
    return p * x;
}

// PRECISE gumbel = -log(-log(max(tiny,u))). __logf is NOT usable here:
// near u~1 the inner -log(u) is tiny with O(1) relative error under MUFU.LG2,
// and those are exactly the draws that win the argmax -> chain divergence.
__device__ __forceinline__ float gumbel_precise(uint32_t bits) {
    float u = bits_to_u01(bits);
    float v = fmaxf(u, 1.17549435082228751e-38f);
    return -logf(-logf(v));
}

// ---------------------------------------------------------------------------
// Fill the 4 constant columns of pf_out once
// ---------------------------------------------------------------------------
__global__ void fill_const_kernel(const float* __restrict__ params,
                                  float* __restrict__ pf) {
    const float p0 = params[0], p1 = params[1], p2 = params[2], p3 = params[3];
    const size_t n = (size_t)TT * KK * BB;
    size_t idx = (size_t)blockIdx.x * blockDim.x + threadIdx.x;
    if (idx < n) {
        float* o = pf + idx * 5;
        o[0] = p0; o[1] = p1; o[2] = p2; o[3] = p3;
    }
}

// ---------------------------------------------------------------------------
// Persistent kernel: 1 CTA per batch element b. Warp-specialized + pipelined:
//   warps 0-1 : phase A (eps/vol/weights/logits) + phase C (resample/output)
//   warps 2-17: phase B (64x64 gumbel + argmax), 4 rows each; gumbel
//               generation (B1) is state-independent and overlaps A and C.
// ---------------------------------------------------------------------------
__global__ void __launch_bounds__(NTHREADS, 1)
garch_pf_kernel(const float* __restrict__ obs,     // (B, T, 2)
                const float* __restrict__ vol0,    // (K*B, 1)
                const float* __restrict__ params,  // (4,)
                float* __restrict__ out) {
    const int b    = blockIdx.x;
    const int tid  = threadIdx.x;
    const int lane = tid & 31;
    const int warp = tid >> 5;

    __shared__ uint2 skey[TT];     // per-step key_t
    __shared__ uint2 sckey[TT];    // fold_in(key_t, 1)
    __shared__ float r_s[TT];      // obs[b, t, 0]
    __shared__ float logit_s[KK];
    __shared__ float nv_s[KK], wn_s[KK], q_s[KK];
    __shared__ float vol_s[KK], w_s[KK];
    __shared__ int   idx_s[KK];
    __shared__ float redm_s[2], reds_s[2];

    for (int t = tid; t < TT; t += NTHREADS) {
        uint2 kt = tf2x32(0u, 42u, 0u, (uint32_t)t);
        skey[t]  = kt;
        sckey[t] = tf2x32(kt.x, kt.y, 0u, 1u);
        r_s[t]   = obs[((size_t)b * TT + t) * 2];
    }
    if (warp < 2) {
        const int pa = warp * 32 + lane;
        vol_s[pa] = vol0[pa * BB + b];
        w_s[pa]   = 1.0f / 64.0f;
    }
    const float c0 = params[0], q1 = params[1], q2 = params[2], r1 = params[3];
    const float r1e = 0.001f * r1;
    __syncthreads();

    float* __restrict__ y_out = out;                    // (T, B, 1)
    float* __restrict__ pf    = out + (size_t)TT * BB;  // (T, K*B, 5)

    const float MINVAL_N = -0.99999994039535522f;
    const float SQRT2    = 1.41421356237309515f;
    const float LOG2PI   = 1.83787706640934534f;
    const float ALPHA_F  = 0.3f;
    const float UNIFW    = (float)((1.0 - 0.3) / 64.0);

    // B-warp row assignment
    const int w2 = warp - 2;                 // 0..15 for B warps
    float g1v[4], g2v[4];                    // per-row gumbels (no logit yet)

    for (int t = 0; t < TT; t++) {
        if (warp < 2) {
            // ---------------- Phase A: 1 particle/lane across warps 0-1 ----
            const uint2 kt = skey[t];
            const float r    = r_s[t];
            const float rr   = r * r;
            const float q2rr = (q2 * r) * r;
            const int pa = warp * 32 + lane;

            uint2 bl = tf2x32(kt.x, kt.y, 0u, (uint32_t)(pa * BB + b));
            float u  = bits_to_u01(bl.x ^ bl.y);
            float v  = fmaxf(MINVAL_N, u * 2.0f + MINVAL_N);
            float eps = SQRT2 * erfinv_xla(v);
            float x   = ((c0 + q1 * vol_s[pa]) + q2rr) + r1e * eps;
            float nvv = fabsf(x) + 1e-8f;
            float ll  = -0.5f * ((rr / nvv + logf(nvv)) + LOG2PI);
            float lw  = logf(w_s[pa] + 1e-12f) + ll;

            // logsumexp over 64 across the two warps
            float m = lw;
#pragma unroll
            for (int o = 16; o; o >>= 1)
                m = fmaxf(m, __shfl_xor_sync(0xffffffffu, m, o));
            if (lane == 0) redm_s[warp] = m;
            asm volatile("bar.sync 1, 64;" ::: "memory");
            float mm = fmaxf(redm_s[0], redm_s[1]);
            float e  = expf(lw - mm);
            float s  = e;
#pragma unroll
            for (int o = 16; o; o >>= 1)
                s += __shfl_xor_sync(0xffffffffu, s, o);
            if (lane == 0) reds_s[warp] = s;
            asm volatile("bar.sync 1, 64;" ::: "memory");
            float lse = logf(reds_s[0] + reds_s[1]) + mm;

            float wn = expf(lw - lse);
            float q  = ALPHA_F * wn + UNIFW;
            nv_s[pa]    = nvv;
            wn_s[pa]    = wn;
            q_s[pa]     = q;
            logit_s[pa] = logf(q);
        } else {
            // ---------------- Phase B1: state-independent gumbels ----------
            const uint2 ck = sckey[t];
            const uint32_t bb64 = (uint32_t)(b * KK);
#pragma unroll
            for (int ii = 0; ii < 4; ii++) {
                const uint32_t i  = (uint32_t)(w2 * 4 + ii);
                const uint32_t cb = i * 8192u + bb64;   // i*B*K + b*K
                uint2 ga = tf2x32(ck.x, ck.y, 0u, cb + (uint32_t)lane);
                uint2 gb = tf2x32(ck.x, ck.y, 0u, cb + (uint32_t)lane + 32u);
                g1v[ii] = gumbel_precise(ga.x ^ ga.y);
                g2v[ii] = gumbel_precise(gb.x ^ gb.y);
            }
        }
        __syncthreads();   // logits published; B1 done

        if (warp >= 2) {
            // ---------------- Phase B2: + logit, argmax --------------------
            const float la = logit_s[lane];
            const float lb = logit_s[lane + 32];
#pragma unroll
            for (int ii = 0; ii < 4; ii++) {
                float s1 = g1v[ii] + la;
                float s2 = g2v[ii] + lb;
                float best; int bj;
                if (s2 > s1) { best = s2; bj = lane + 32; }
                else         { best = s1; bj = lane; }
#pragma unroll
                for (int o = 16; o; o >>= 1) {
                    float ov = __shfl_xor_sync(0xffffffffu, best, o);
                    int   oj = __shfl_xor_sync(0xffffffffu, bj, o);
                    if (ov > best || (ov == best && oj < bj)) { best = ov; bj = oj; }
                }
                if (lane == 0) idx_s[w2 * 4 + ii] = bj;
            }
        }
        __syncthreads();   // idx published; B warps now free-run into B1(t+1)

        if (warp < 2) {
            // ---------------- Phase C: resample, normalize, outputs --------
            if (warp == 0) {
                const int ia = idx_s[lane], ib = idx_s[lane + 32];
                float vra = nv_s[ia], vrb = nv_s[ib];
                float wra = wn_s[ia] / q_s[ia];
                float wrb = wn_s[ib] / q_s[ib];
                float ssum = wra + wrb;
#pragma unroll
                for (int o = 16; o; o >>= 1)
                    ssum += __shfl_xor_sync(0xffffffffu, ssum, o);
                wra /= ssum; wrb /= ssum;
                vol_s[lane]      = vra; vol_s[lane + 32] = vrb;
                w_s[lane]        = wra; w_s[lane + 32]   = wrb;
                float y = vra * wra + vrb * wrb;
#pragma unroll
                for (int o = 16; o; o >>= 1)
                    y += __shfl_xor_sync(0xffffffffu, y, o);
                if (lane == 0) y_out[(size_t)t * BB + b] = y;
                pf[((size_t)t * (KK * BB) + (size_t)lane * BB + b) * 5 + 4] = vra;
                pf[((size_t)t * (KK * BB) + (size_t)(lane + 32) * BB + b) * 5 + 4] = vrb;
            }
            // warp1 waits for C's state writes before A(t+1)
            asm volatile("bar.sync 1, 64;" ::: "memory");
        }
    }
}

// ---------------------------------------------------------------------------
extern "C" void kernel_launch(void* const* d_in, const int* in_sizes, int n_in,
                              void* d_out, int out_size) {
    const float* obs    = (const float*)d_in[0];  // (128, 2048, 2)
    const float* vol0   = (const float*)d_in[1];  // (8192, 1)
    const float* params = (const float*)d_in[2];  // (4,)
    float* out = (float*)d_out;

    float* pf = out + (size_t)TT * BB;
    fill_const_kernel<<<65536, 256>>>(params, pf);
    garch_pf_kernel<<<BB, NTHREADS>>>(obs, vol0, params, out);
}